// round 13
// baseline (speedup 1.0000x reference)
#include <cuda_runtime.h>
#include <cuda_fp16.h>
#include <cstdint>

#define NN   8192
#define F    768
#define HIDD 384
#define OUTD 10
#define NNZ  (NN * 16)
#define DCAT (F + 2 * HIDD)

#define STAGES  3
#define ABYTES  (128 * 128)        // A tile: 128 rows x 128 B (= 64 halves/row)

// ---------------- scratch (device globals; no allocation allowed) ----------------
__device__ __align__(16) __half g_xn16[NN * F];
__device__ __align__(16) float  g_xt[NN * F];
__device__ __align__(16) float  g_efeat[NN * F];
__device__ __align__(16) float  g_h[NN * F];
__device__ __align__(16) __half g_h16[NN * F];
__device__ __align__(16) float  g_out1[NN * HIDD];
__device__ __align__(16) float  g_out2[NN * HIDD];
__device__ __align__(16) __half g_catT16[(size_t)DCAT * NN];
__device__ __align__(16) __half g_w1h[(size_t)NN * NN];   // attn_W1 fp16
__device__ __align__(16) __half g_wh[F * F];              // hg W fp16
__device__ __align__(16) __half g_fwh[HIDD * F];          // fc W fp16
__device__ float    g_alpha[NNZ];
__device__ float    g_ax[NN];
__device__ float    g_ae[NN];
__device__ float    g_wv[F];          // W^T @ att[F:]
__device__ float    g_score[DCAT];
__device__ float    g_wp[OUTD * DCAT];
__device__ float    g_colsum[F];
__device__ float    g_colsq[F];
// CSR structures (built once; edge_index identical for both convs)
__device__ int      g_cnt_c[NN], g_cnt_r[NN];
__device__ int      g_cur_c[NN], g_cur_r[NN];
__device__ int      g_off_c[NN + 1], g_off_r[NN + 1];
__device__ int      g_perm_c[NNZ], g_perm_r[NNZ];

// ---------------- PTX helpers (plain sm_103-safe, sm_80 features) ----------------
__device__ __forceinline__ uint32_t smem_u32(const void* p) {
    uint32_t a;
    asm("{ .reg .u64 t; cvta.to.shared.u64 t, %1; cvt.u32.u64 %0, t; }" : "=r"(a) : "l"(p));
    return a;
}
#define CP_ASYNC16(d, s) \
    asm volatile("cp.async.cg.shared.global [%0], [%1], 16;" :: "r"(d), "l"(s) : "memory")
#define CP_COMMIT()      asm volatile("cp.async.commit_group;" ::: "memory")
#define CP_WAIT(n)       asm volatile("cp.async.wait_group %0;" :: "n"(n) : "memory")

__device__ __forceinline__ void mma_f16(float* c, const uint32_t* a, const uint32_t* b) {
    asm volatile(
        "mma.sync.aligned.m16n8k16.row.col.f32.f16.f16.f32 "
        "{%0,%1,%2,%3}, {%4,%5,%6,%7}, {%8,%9}, {%0,%1,%2,%3};"
        : "+f"(c[0]), "+f"(c[1]), "+f"(c[2]), "+f"(c[3])
        : "r"(a[0]), "r"(a[1]), "r"(a[2]), "r"(a[3]), "r"(b[0]), "r"(b[1]));
}

// ---------------- fp16 mma.sync NT GEMM: C[M,Nc] = A[M,K] * B[Nc,K]^T ----------------
// A,B fp16 row-major K-contiguous. CTA tile 128 x NT, 8 warps (2M x 4N), warp 64 x NT/4.
// K-chunk = 64 halves (128 B/row), fragment layout of m16n8k16.f16 matches the same
// off0/off1 + row-pair addressing as the old tf32 kernel.
// mode 0: store C (fp32). mode 1: C = lrelu(acc + bias[col], 0.01).
// mode 2: no C; score[row] += sum_col relu(acc + bias[col]) * w2[col].
template <int NT>
__global__ void __launch_bounds__(256, 1) k_gemm(
    const __half* __restrict__ A, const __half* __restrict__ B, float* __restrict__ C,
    int Nc, int K, int mode,
    const float* __restrict__ bias, const float* __restrict__ w2,
    float* __restrict__ score)
{
    constexpr int N8     = NT / 32;            // n8 tiles per warp (8 or 4)
    constexpr int BBYTES = NT * 128;
    constexpr int STB    = ABYTES + BBYTES;
    extern __shared__ char dsmem[];
    __shared__ float red[128];

    const int tid  = threadIdx.x;
    const int warp = tid >> 5;
    const int lane = tid & 31;
    const int qid  = lane >> 2;
    const int kid  = lane & 3;
    const int wm   = (warp >> 2) * 64;
    const int wn   = (warp & 3) * (NT / 4);
    const int row0 = blockIdx.y * 128;
    const int col0 = blockIdx.x * NT;
    const int nch  = K / 64;                   // 64 halves per chunk
    const uint32_t sw = (uint32_t)qid * 16;
    const uint32_t sm0   = smem_u32(dsmem);
    const uint32_t data0 = (sm0 + 1023u) & ~1023u;

    float c[4][N8][4];
#pragma unroll
    for (int i = 0; i < 4; i++)
#pragma unroll
        for (int j = 0; j < N8; j++)
#pragma unroll
            for (int k = 0; k < 4; k++) c[i][j][k] = 0.f;

    auto load_chunk = [&](int ch, int s) {
        const int k0 = ch * 64;
        const uint32_t sa = data0 + (uint32_t)s * STB;
        const uint32_t sb = sa + ABYTES;
        const __half* Ag = A + (size_t)row0 * K + k0;
        const __half* Bg = B + (size_t)col0 * K + k0;
#pragma unroll
        for (int w = 0; w < 4; w++) {              // 128 rows x 8 x 16B
            int idx = tid + w * 256;
            int r = idx >> 3, c4 = idx & 7;
            uint32_t off = (uint32_t)r * 128 + (((uint32_t)c4 * 16) ^ (((uint32_t)r & 7) * 16));
            CP_ASYNC16(sa + off, Ag + (size_t)r * K + c4 * 8);
        }
#pragma unroll
        for (int w = 0; w < NT / 32; w++) {        // NT rows x 8 x 16B
            int idx = tid + w * 256;
            int r = idx >> 3, c4 = idx & 7;
            uint32_t off = (uint32_t)r * 128 + (((uint32_t)c4 * 16) ^ (((uint32_t)r & 7) * 16));
            CP_ASYNC16(sb + off, Bg + (size_t)r * K + c4 * 8);
        }
        CP_COMMIT();
    };

    for (int i = 0; i < STAGES; i++) load_chunk(i, i);

    for (int i = 0; i < nch; i++) {
        const int s = i % STAGES;
        CP_WAIT(STAGES - 1);
        __syncthreads();

        const char* sA = dsmem + ((data0 - sm0) + (uint32_t)s * STB);
        const char* sB = sA + ABYTES;
#pragma unroll
        for (int k16 = 0; k16 < 4; k16++) {        // 4 x K=16 slabs per 64-half chunk
            const uint32_t x0   = (uint32_t)(k16 * 32 + kid * 4);
            const uint32_t off0 = x0 ^ sw;
            const uint32_t off1 = (x0 + 16) ^ sw;
            uint32_t a[4][4], b[N8][2];
#pragma unroll
            for (int mt = 0; mt < 4; mt++) {
                const char* p = sA + (size_t)(wm + mt * 16 + qid) * 128;
                a[mt][0] = *(const uint32_t*)(p + off0);
                a[mt][1] = *(const uint32_t*)(p + 1024 + off0);
                a[mt][2] = *(const uint32_t*)(p + off1);
                a[mt][3] = *(const uint32_t*)(p + 1024 + off1);
            }
#pragma unroll
            for (int nt = 0; nt < N8; nt++) {
                const char* p = sB + (size_t)(wn + nt * 8 + qid) * 128;
                b[nt][0] = *(const uint32_t*)(p + off0);
                b[nt][1] = *(const uint32_t*)(p + off1);
            }
#pragma unroll
            for (int mt = 0; mt < 4; mt++)
#pragma unroll
                for (int nt = 0; nt < N8; nt++)
                    mma_f16(c[mt][nt], a[mt], b[nt]);
        }
        __syncthreads();
        if (i + STAGES < nch) load_chunk(i + STAGES, s);
        else                  CP_COMMIT();
    }

    // ---------------- epilogue ----------------
    if (mode == 2) {
        float bv[N8 * 2], wv[N8 * 2];
#pragma unroll
        for (int nt = 0; nt < N8; nt++)
#pragma unroll
            for (int j = 0; j < 2; j++) {
                int col = col0 + wn + nt * 8 + kid * 2 + j;
                bv[nt * 2 + j] = bias[col];
                wv[nt * 2 + j] = w2[col];
            }
        if (tid < 128) red[tid] = 0.f;
        __syncthreads();
#pragma unroll
        for (int mt = 0; mt < 4; mt++)
#pragma unroll
            for (int h = 0; h < 2; h++) {
                float part = 0.f;
#pragma unroll
                for (int nt = 0; nt < N8; nt++)
#pragma unroll
                    for (int j = 0; j < 2; j++) {
                        float v = c[mt][nt][h * 2 + j] + bv[nt * 2 + j];
                        part = fmaf(fmaxf(v, 0.f), wv[nt * 2 + j], part);
                    }
                part += __shfl_xor_sync(0xffffffffu, part, 1);
                part += __shfl_xor_sync(0xffffffffu, part, 2);
                if (kid == 0)
                    atomicAdd(&red[wm + mt * 16 + qid + h * 8], part);
            }
        __syncthreads();
        if (tid < 128) atomicAdd(&score[row0 + tid], red[tid]);
        return;
    }

#pragma unroll
    for (int mt = 0; mt < 4; mt++)
#pragma unroll
        for (int h = 0; h < 2; h++) {
            int row = row0 + wm + mt * 16 + qid + h * 8;
            float* Cp = C + (size_t)row * Nc + col0 + wn;
#pragma unroll
            for (int nt = 0; nt < N8; nt++) {
                float v0 = c[mt][nt][h * 2 + 0];
                float v1 = c[mt][nt][h * 2 + 1];
                int coll = wn + nt * 8 + kid * 2;
                if (mode == 1) {
                    v0 += bias[col0 + coll];
                    v1 += bias[col0 + coll + 1];
                    v0 = v0 >= 0.f ? v0 : 0.01f * v0;
                    v1 = v1 >= 0.f ? v1 : 0.01f * v1;
                }
                *(float2*)(Cp + nt * 8 + kid * 2) = make_float2(v0, v1);
            }
        }
}

// ---------------- fp16 pre-conversion ----------------
__global__ void k_cvt_h(const float4* __restrict__ src, __half2* __restrict__ dst, int n4) {
    int i = blockIdx.x * blockDim.x + threadIdx.x;
    if (i >= n4) return;
    float4 v = src[i];
    dst[2 * i]     = __floats2half2_rn(v.x, v.y);
    dst[2 * i + 1] = __floats2half2_rn(v.z, v.w);
}

// ---------------- wv = W^T @ att[F:]  (et GEMM eliminated) ----------------
__global__ void k_watt(const float* __restrict__ W, const float* __restrict__ att) {
    int k = blockIdx.x * blockDim.x + threadIdx.x;
    if (k >= F) return;
    float s = 0.f;
    for (int f = 0; f < F; f++) s = fmaf(W[f * F + k], att[F + f], s);
    g_wv[k] = s;
}

// ---------------- CSR build (once) ----------------
__global__ void k_csr_zero() {
    int i = blockIdx.x * blockDim.x + threadIdx.x;
    if (i < NN) { g_cnt_c[i] = 0; g_cnt_r[i] = 0; g_cur_c[i] = 0; g_cur_r[i] = 0; }
}
__global__ void k_csr_count(const int* __restrict__ ei) {
    int e = blockIdx.x * blockDim.x + threadIdx.x;
    if (e >= NNZ) return;
    atomicAdd(&g_cnt_c[ei[NNZ + e]], 1);
    atomicAdd(&g_cnt_r[ei[e]], 1);
}
// exclusive scans of both 8192-int histograms; block 0 -> col, block 1 -> row
__global__ void k_scan2() {
    __shared__ int part[1024];
    const int* cnt = blockIdx.x ? g_cnt_r : g_cnt_c;
    int*       off = blockIdx.x ? g_off_r : g_off_c;
    int t = threadIdx.x;
    int loc[8];
    int s = 0;
#pragma unroll
    for (int i = 0; i < 8; i++) { loc[i] = s; s += cnt[t * 8 + i]; }
    part[t] = s;
    __syncthreads();
    for (int d = 1; d < 1024; d <<= 1) {
        int v = (t >= d) ? part[t - d] : 0;
        __syncthreads();
        part[t] += v;
        __syncthreads();
    }
    int base = (t == 0) ? 0 : part[t - 1];
#pragma unroll
    for (int i = 0; i < 8; i++) off[t * 8 + i] = base + loc[i];
    if (t == 1023) off[NN] = part[1023];
}
__global__ void k_csr_place(const int* __restrict__ ei) {
    int e = blockIdx.x * blockDim.x + threadIdx.x;
    if (e >= NNZ) return;
    int r = ei[e], c = ei[NNZ + e];
    int pc = atomicAdd(&g_cur_c[c], 1);
    g_perm_c[g_off_c[c] + pc] = e;
    int pr = atomicAdd(&g_cur_r[r], 1);
    g_perm_r[g_off_r[r] + pr] = e;
}

// ---------------- small utility kernels ----------------
__global__ void k_zero_gn() {
    int c = threadIdx.x;
    if (c < F) { g_colsum[c] = 0.f; g_colsq[c] = 0.f; }
}
__global__ void k_zero_score() {
    int d = blockIdx.x * blockDim.x + threadIdx.x;
    if (d < DCAT) g_score[d] = 0.f;
}

// ---------------- GraphNorm ----------------
__global__ void k_gn_reduce(const float* __restrict__ X) {
    int c  = threadIdx.x;
    int r0 = blockIdx.x * 64;
    float s = 0.f, q = 0.f;
    for (int i = 0; i < 64; i++) {
        float v = X[(size_t)(r0 + i) * F + c];
        s += v;
        q += v * v;
    }
    atomicAdd(&g_colsum[c], s);
    atomicAdd(&g_colsq[c], q);
}

__global__ void k_gn_apply(const float* __restrict__ X,
                           const float* __restrict__ w,
                           const float* __restrict__ b,
                           const float* __restrict__ ms) {
    int idx = blockIdx.x * blockDim.x + threadIdx.x;
    if (idx >= NN * F) return;
    int c = idx % F;
    float invN  = 1.f / (float)NN;
    float mean  = g_colsum[c] * invN;
    float m     = ms[c];
    float var   = g_colsq[c] * invN - m * (2.f - m) * mean * mean;
    float outv  = X[idx] - m * mean;
    g_xn16[idx] = __float2half_rn(w[c] * outv * rsqrtf(var + 1e-5f) + b[c]);
}

// ---------------- ax = xt@att[:F], ae = eattr@wv ----------------
__global__ void k_gemv_att(const float* __restrict__ att, const float* __restrict__ eattr) {
    int w    = (blockIdx.x * blockDim.x + threadIdx.x) >> 5;
    int lane = threadIdx.x & 31;
    if (w >= NN) return;
    const float* xr = g_xt + (size_t)w * F;
    const float* er = eattr + (size_t)w * F;
    float s1 = 0.f, s2 = 0.f;
    for (int i = lane; i < F; i += 32) {
        s1 = fmaf(xr[i], att[i],  s1);
        s2 = fmaf(er[i], g_wv[i], s2);
    }
#pragma unroll
    for (int off = 16; off; off >>= 1) {
        s1 += __shfl_xor_sync(0xffffffffu, s1, off);
        s2 += __shfl_xor_sync(0xffffffffu, s2, off);
    }
    if (lane == 0) { g_ax[w] = s1; g_ae[w] = s2; }
}

// ---------------- fused per-hyperedge softmax (warp per segment) ----------------
__global__ void k_seg_softmax(const int* __restrict__ ei) {
    int w    = (blockIdx.x * blockDim.x + threadIdx.x) >> 5;
    int lane = threadIdx.x & 31;
    if (w >= NN) return;
    int s = g_off_c[w], n = g_off_c[w + 1] - s;
    if (n == 0) return;
    float aec = g_ae[w];
    float m = -3.4e38f;
    for (int i = lane; i < n; i += 32) {
        int e = g_perm_c[s + i];
        float a = g_ax[ei[e]] + aec;
        a = a >= 0.f ? a : 0.2f * a;
        g_alpha[e] = a;
        m = fmaxf(m, a);
    }
#pragma unroll
    for (int o = 16; o; o >>= 1) m = fmaxf(m, __shfl_xor_sync(0xffffffffu, m, o));
    float sum = 0.f;
    for (int i = lane; i < n; i += 32) {
        int e = g_perm_c[s + i];
        float ex = expf(g_alpha[e] - m);
        g_alpha[e] = ex;
        sum += ex;
    }
#pragma unroll
    for (int o = 16; o; o >>= 1) sum += __shfl_xor_sync(0xffffffffu, sum, o);
    float inv = 1.f / (sum + 1e-16f);
    for (int i = lane; i < n; i += 32) g_alpha[g_perm_c[s + i]] *= inv;
}

// ---------------- atomic-free scatters: block per segment ----------------
#define SCH 64
__global__ void k_scatter_e(const int* __restrict__ ei) {   // node -> hyperedge
    __shared__ float scoef[SCH];
    __shared__ int   sidx[SCH];
    int c = blockIdx.x;
    int s = g_off_c[c], end = g_off_c[c + 1];
    int n = end - s;
    float bn = n > 0 ? 1.f / (float)n : 0.f;
    int f = threadIdx.x * 4;
    float4 acc = make_float4(0.f, 0.f, 0.f, 0.f);
    while (s < end) {
        int chunk = min(SCH, end - s);
        __syncthreads();
        if ((int)threadIdx.x < chunk) {
            int e = g_perm_c[s + threadIdx.x];
            scoef[threadIdx.x] = bn * g_alpha[e];
            sidx[threadIdx.x]  = ei[e];                 // row
        }
        __syncthreads();
        for (int j = 0; j < chunk; j++) {
            float cf = scoef[j];
            float4 v = *(const float4*)&g_xt[(size_t)sidx[j] * F + f];
            acc.x = fmaf(cf, v.x, acc.x);
            acc.y = fmaf(cf, v.y, acc.y);
            acc.z = fmaf(cf, v.z, acc.z);
            acc.w = fmaf(cf, v.w, acc.w);
        }
        s += chunk;
    }
    *(float4*)&g_efeat[(size_t)c * F + f] = acc;
}

__global__ void k_scatter_n(const int* __restrict__ ei, const float* __restrict__ bias) {
    __shared__ float scoef[SCH];
    __shared__ int   sidx[SCH];
    int r = blockIdx.x;
    int s = g_off_r[r], end = g_off_r[r + 1];
    int n = end - s;
    float dn = n > 0 ? 1.f / (float)n : 0.f;
    int f = threadIdx.x * 4;
    float4 acc = make_float4(0.f, 0.f, 0.f, 0.f);
    while (s < end) {
        int chunk = min(SCH, end - s);
        __syncthreads();
        if ((int)threadIdx.x < chunk) {
            int e = g_perm_r[s + threadIdx.x];
            scoef[threadIdx.x] = dn * g_alpha[e];
            sidx[threadIdx.x]  = ei[NNZ + e];           // col
        }
        __syncthreads();
        for (int j = 0; j < chunk; j++) {
            float cf = scoef[j];
            float4 v = *(const float4*)&g_efeat[(size_t)sidx[j] * F + f];
            acc.x = fmaf(cf, v.x, acc.x);
            acc.y = fmaf(cf, v.y, acc.y);
            acc.z = fmaf(cf, v.z, acc.z);
            acc.w = fmaf(cf, v.w, acc.w);
        }
        s += chunk;
    }
    // fused: + bias, leaky relu 0.01; write fp32 (GN input) and fp16 (GEMM input)
    float4 b4 = *(const float4*)&bias[f];
    acc.x += b4.x; acc.y += b4.y; acc.z += b4.z; acc.w += b4.w;
    acc.x = acc.x >= 0.f ? acc.x : 0.01f * acc.x;
    acc.y = acc.y >= 0.f ? acc.y : 0.01f * acc.y;
    acc.z = acc.z >= 0.f ? acc.z : 0.01f * acc.z;
    acc.w = acc.w >= 0.f ? acc.w : 0.01f * acc.w;
    *(float4*)&g_h[(size_t)r * F + f] = acc;
    __half2* hp = (__half2*)&g_h16[(size_t)r * F + f];
    hp[0] = __floats2half2_rn(acc.x, acc.y);
    hp[1] = __floats2half2_rn(acc.z, acc.w);
}

// ---------------- transpose src[NN,C] -> fp16 dst[c*NN + r] ----------------
__global__ void k_transpose(const float* __restrict__ src, int C, __half* __restrict__ dst) {
    __shared__ float t[32][33];
    int c0 = blockIdx.x * 32, r0 = blockIdx.y * 32;
    int tx = threadIdx.x, ty = threadIdx.y;
#pragma unroll
    for (int i = 0; i < 4; i++)
        t[ty + 8 * i][tx] = src[(size_t)(r0 + ty + 8 * i) * C + c0 + tx];
    __syncthreads();
#pragma unroll
    for (int i = 0; i < 4; i++)
        dst[(size_t)(c0 + ty + 8 * i) * NN + r0 + tx] = __float2half_rn(t[tx][ty + 8 * i]);
}

// ---------------- score finalize + folded classifier ----------------
__global__ void k_score_final(const float* __restrict__ b2, const float* __restrict__ center) {
    int d = blockIdx.x * blockDim.x + threadIdx.x;
    if (d >= DCAT) return;
    float r = g_score[d] + b2[0];
    float sg = 1.f / (1.f + expf(-r));
    g_score[d] = sg - center[d];
}

__global__ void k_wp(const float* __restrict__ clsW) {
    int idx = blockIdx.x * blockDim.x + threadIdx.x;
    if (idx >= OUTD * DCAT) return;
    g_wp[idx] = clsW[idx] * g_score[idx % DCAT];
}

__global__ void k_logits(const float* __restrict__ x, const float* __restrict__ clsb,
                         float* __restrict__ out) {
    int n    = (blockIdx.x * blockDim.x + threadIdx.x) >> 5;
    int lane = threadIdx.x & 31;
    if (n >= NN) return;
    float acc[OUTD];
#pragma unroll
    for (int o = 0; o < OUTD; o++) acc[o] = 0.f;

    const float* xr = x + (size_t)n * F;
#pragma unroll
    for (int it = 0; it < 6; it++) {
        int i = lane * 4 + it * 128;
        float4 v = *(const float4*)&xr[i];
#pragma unroll
        for (int o = 0; o < OUTD; o++) {
            float4 w = *(const float4*)&g_wp[o * DCAT + i];
            acc[o] += v.x * w.x + v.y * w.y + v.z * w.z + v.w * w.w;
        }
    }
    const float* o1 = g_out1 + (size_t)n * HIDD;
#pragma unroll
    for (int it = 0; it < 3; it++) {
        int i = lane * 4 + it * 128;
        float4 v = *(const float4*)&o1[i];
#pragma unroll
        for (int o = 0; o < OUTD; o++) {
            float4 w = *(const float4*)&g_wp[o * DCAT + F + i];
            acc[o] += v.x * w.x + v.y * w.y + v.z * w.z + v.w * w.w;
        }
    }
    const float* o2 = g_out2 + (size_t)n * HIDD;
#pragma unroll
    for (int it = 0; it < 3; it++) {
        int i = lane * 4 + it * 128;
        float4 v = *(const float4*)&o2[i];
#pragma unroll
        for (int o = 0; o < OUTD; o++) {
            float4 w = *(const float4*)&g_wp[o * DCAT + F + HIDD + i];
            acc[o] += v.x * w.x + v.y * w.y + v.z * w.z + v.w * w.w;
        }
    }
#pragma unroll
    for (int o = 0; o < OUTD; o++) {
        float v = acc[o];
#pragma unroll
        for (int off = 16; off; off >>= 1) v += __shfl_xor_sync(0xffffffffu, v, off);
        if (lane == 0) out[(size_t)n * OUTD + o] = v + clsb[o];
    }
}

// ---------------- host-side driver ----------------
static const int SMEM256 = STAGES * (ABYTES + 256 * 128) + 1024;  // 148480
static const int SMEM128 = STAGES * (ABYTES + 128 * 128) + 1024;  //  99328

static void run_conv(const float* feat_in, const int* ei, const float* eattr,
                     const float* gw, const float* gb, const float* gms,
                     const float* W, const float* att, const float* hb,
                     __half* p_xn16, __half* p_wh, float* p_xt)
{
    k_zero_gn<<<1, 768>>>();
    k_gn_reduce<<<NN / 64, 768>>>(feat_in);
    k_gn_apply<<<NN * F / 256, 256>>>(feat_in, gw, gb, gms);
    k_cvt_h<<<(F * F / 4 + 255) / 256, 256>>>((const float4*)W, (__half2*)p_wh, F * F / 4);
    k_watt<<<(F + 255) / 256, 256>>>(W, att);
    k_gemm<256><<<dim3(F / 256, NN / 128), 256, SMEM256>>>(
        p_xn16, p_wh, p_xt, F, F, 0, nullptr, nullptr, nullptr);
    k_gemv_att<<<NN / 8, 256>>>(att, eattr);
    k_seg_softmax<<<NN / 8, 256>>>(ei);
    k_scatter_e<<<NN, 192>>>(ei);
    k_scatter_n<<<NN, 192>>>(ei, hb);
}

extern "C" void kernel_launch(void* const* d_in, const int* in_sizes, int n_in,
                              void* d_out, int out_size) {
    const float* x       = (const float*)d_in[0];
    const int*   ei      = (const int*)  d_in[1];
    const float* eattr   = (const float*)d_in[2];
    const float* gn1_w   = (const float*)d_in[3];
    const float* gn1_b   = (const float*)d_in[4];
    const float* gn1_ms  = (const float*)d_in[5];
    const float* gn2_w   = (const float*)d_in[6];
    const float* gn2_b   = (const float*)d_in[7];
    const float* gn2_ms  = (const float*)d_in[8];
    const float* hg1_W   = (const float*)d_in[9];
    const float* hg1_att = (const float*)d_in[10];
    const float* hg1_b   = (const float*)d_in[11];
    const float* hg2_W   = (const float*)d_in[12];
    const float* hg2_att = (const float*)d_in[13];
    const float* hg2_b   = (const float*)d_in[14];
    const float* fc1_W   = (const float*)d_in[15];
    const float* fc1_b   = (const float*)d_in[16];
    const float* fc2_W   = (const float*)d_in[17];
    const float* fc2_b   = (const float*)d_in[18];
    const float* attn_W1 = (const float*)d_in[19];
    const float* attn_b1 = (const float*)d_in[20];
    const float* attn_W2 = (const float*)d_in[21];
    const float* attn_b2 = (const float*)d_in[22];
    const float* cls_W   = (const float*)d_in[23];
    const float* cls_b   = (const float*)d_in[24];
    const float* center  = (const float*)d_in[25];
    float*       out     = (float*)d_out;

    cudaFuncSetAttribute(k_gemm<256>, cudaFuncAttributeMaxDynamicSharedMemorySize, SMEM256);
    cudaFuncSetAttribute(k_gemm<128>, cudaFuncAttributeMaxDynamicSharedMemorySize, SMEM128);

    float *p_xt, *p_h, *p_out1, *p_out2, *p_score;
    __half *p_xn16, *p_h16, *p_catT16, *p_w1h, *p_wh, *p_fwh;
    cudaGetSymbolAddress((void**)&p_xt,      g_xt);
    cudaGetSymbolAddress((void**)&p_h,       g_h);
    cudaGetSymbolAddress((void**)&p_out1,    g_out1);
    cudaGetSymbolAddress((void**)&p_out2,    g_out2);
    cudaGetSymbolAddress((void**)&p_score,   g_score);
    cudaGetSymbolAddress((void**)&p_xn16,    g_xn16);
    cudaGetSymbolAddress((void**)&p_h16,     g_h16);
    cudaGetSymbolAddress((void**)&p_catT16,  g_catT16);
    cudaGetSymbolAddress((void**)&p_w1h,     g_w1h);
    cudaGetSymbolAddress((void**)&p_wh,      g_wh);
    cudaGetSymbolAddress((void**)&p_fwh,     g_fwh);

    // ---- CSR build (once) + big one-time fp16 conversion ----
    k_csr_zero<<<NN / 256, 256>>>();
    k_csr_count<<<NNZ / 256, 256>>>(ei);
    k_scan2<<<2, 1024>>>();
    k_csr_place<<<NNZ / 256, 256>>>(ei);
    k_cvt_h<<<(int)((size_t)NN * NN / 4 / 256), 256>>>((const float4*)attn_W1, (__half2*)p_w1h,
                                                       (int)((size_t)NN * NN / 4));

    // ---- conv1 + fc1 ----
    run_conv(x, ei, eattr, gn1_w, gn1_b, gn1_ms, hg1_W, hg1_att, hg1_b, p_xn16, p_wh, p_xt);
    k_cvt_h<<<(HIDD * F / 4 + 255) / 256, 256>>>((const float4*)fc1_W, (__half2*)p_fwh, HIDD * F / 4);
    k_gemm<128><<<dim3(HIDD / 128, NN / 128), 256, SMEM128>>>(
        p_h16, p_fwh, p_out1, HIDD, F, 1, fc1_b, nullptr, nullptr);

    // ---- conv2 (graphnorm reads fp32 g_h = h1 before scatter_n overwrites it) + fc2 ----
    run_conv(p_h, ei, eattr, gn2_w, gn2_b, gn2_ms, hg2_W, hg2_att, hg2_b, p_xn16, p_wh, p_xt);
    k_cvt_h<<<(HIDD * F / 4 + 255) / 256, 256>>>((const float4*)fc2_W, (__half2*)p_fwh, HIDD * F / 4);
    k_gemm<128><<<dim3(HIDD / 128, NN / 128), 256, SMEM128>>>(
        p_h16, p_fwh, p_out2, HIDD, F, 1, fc2_b, nullptr, nullptr);

    // ---- catT = [x; out1; out2]^T in fp16 (node-contiguous) ----
    k_transpose<<<dim3(F / 32,    NN / 32), dim3(32, 8)>>>(x,      F,    p_catT16);
    k_transpose<<<dim3(HIDD / 32, NN / 32), dim3(32, 8)>>>(p_out1, HIDD, p_catT16 + (size_t)F * NN);
    k_transpose<<<dim3(HIDD / 32, NN / 32), dim3(32, 8)>>>(p_out2, HIDD, p_catT16 + (size_t)(F + HIDD) * NN);

    // ---- attention: score[d] = sum_j relu(catT@W1^T + b1)[d,j] * W2[j] (fused epilogue) ----
    k_zero_score<<<(DCAT + 255) / 256, 256>>>();
    k_gemm<256><<<dim3(NN / 256, DCAT / 128), 256, SMEM256>>>(
        p_catT16, p_w1h, nullptr, NN, NN, 2, attn_b1, attn_W2, p_score);
    k_score_final<<<(DCAT + 255) / 256, 256>>>(attn_b2, center);

    // ---- classifier with score folded into weights ----
    k_wp<<<(OUTD * DCAT + 255) / 256, 256>>>(cls_W);
    k_logits<<<NN * 32 / 256, 256>>>(x, cls_b, out);
}

// round 14
// speedup vs baseline: 1.0203x; 1.0203x over previous
#include <cuda_runtime.h>
#include <cuda_fp16.h>
#include <cstdint>

#define NN   8192
#define F    768
#define HIDD 384
#define OUTD 10
#define NNZ  (NN * 16)
#define DCAT (F + 2 * HIDD)

#define STAGES  3
#define ABYTES  (128 * 128)        // A tile: 128 rows x 128 B (= 64 halves/row)

// ---------------- scratch (device globals; no allocation allowed) ----------------
__device__ __align__(16) __half g_xn16[NN * F];
__device__ __align__(16) __half g_xt16[NN * F];
__device__ __align__(16) __half g_ef16[NN * F];
__device__ __align__(16) float  g_h[NN * F];
__device__ __align__(16) __half g_h16[NN * F];
__device__ __align__(16) float  g_out1[NN * HIDD];
__device__ __align__(16) float  g_out2[NN * HIDD];
__device__ __align__(16) __half g_catT16[(size_t)DCAT * NN];
__device__ __align__(16) __half g_w1h[(size_t)NN * NN];   // attn_W1 fp16
__device__ __align__(16) __half g_wh[F * F];              // hg W fp16
__device__ __align__(16) __half g_fwh[HIDD * F];          // fc W fp16
__device__ float    g_alpha[NNZ];
__device__ float    g_ax[NN];
__device__ float    g_ae[NN];
__device__ float    g_wv[F];          // W^T @ att[F:]
__device__ float    g_score[DCAT];
__device__ float    g_wp[OUTD * DCAT];
__device__ float    g_colsum[F];
__device__ float    g_colsq[F];
// CSR structures (built once; edge_index identical for both convs)
__device__ int      g_cnt_c[NN], g_cnt_r[NN];
__device__ int      g_cur_c[NN], g_cur_r[NN];
__device__ int      g_off_c[NN + 1], g_off_r[NN + 1];
__device__ int      g_perm_c[NNZ], g_perm_r[NNZ];

// ---------------- PTX helpers (plain sm_103-safe, sm_80 features) ----------------
__device__ __forceinline__ uint32_t smem_u32(const void* p) {
    uint32_t a;
    asm("{ .reg .u64 t; cvta.to.shared.u64 t, %1; cvt.u32.u64 %0, t; }" : "=r"(a) : "l"(p));
    return a;
}
#define CP_ASYNC16(d, s) \
    asm volatile("cp.async.cg.shared.global [%0], [%1], 16;" :: "r"(d), "l"(s) : "memory")
#define CP_COMMIT()      asm volatile("cp.async.commit_group;" ::: "memory")
#define CP_WAIT(n)       asm volatile("cp.async.wait_group %0;" :: "n"(n) : "memory")

#define LDSM4(r0, r1, r2, r3, addr) \
    asm volatile("ldmatrix.sync.aligned.m8n8.x4.shared.b16 {%0,%1,%2,%3}, [%4];" \
                 : "=r"(r0), "=r"(r1), "=r"(r2), "=r"(r3) : "r"(addr))

__device__ __forceinline__ void mma_f16(float* c, const uint32_t* a, const uint32_t* b) {
    asm volatile(
        "mma.sync.aligned.m16n8k16.row.col.f32.f16.f16.f32 "
        "{%0,%1,%2,%3}, {%4,%5,%6,%7}, {%8,%9}, {%0,%1,%2,%3};"
        : "+f"(c[0]), "+f"(c[1]), "+f"(c[2]), "+f"(c[3])
        : "r"(a[0]), "r"(a[1]), "r"(a[2]), "r"(a[3]), "r"(b[0]), "r"(b[1]));
}

// ---------------- fp16 mma.sync NT GEMM: C[M,Nc] = A[M,K] * B[Nc,K]^T ----------------
// CTA tile 128 x NT, 8 warps (2M x 4N), warp tile 64 x NT/4. K-chunk = 64 halves.
// ldmatrix.x4 fragment loads (verified identical layout to the scalar-load version).
// swapgrid=1: row tiles on blockIdx.x (consecutive CTAs share B panel -> L2 reuse).
// mode 0: store C fp16. mode 1: C fp32 = lrelu(acc + bias[col], 0.01).
// mode 2: no C; score[row] += sum_col relu(acc + bias[col]) * w2[col].
template <int NT>
__global__ void __launch_bounds__(256, 1) k_gemm(
    const __half* __restrict__ A, const __half* __restrict__ B, void* __restrict__ Cv,
    int Nc, int K, int mode, int swapgrid,
    const float* __restrict__ bias, const float* __restrict__ w2,
    float* __restrict__ score)
{
    constexpr int N8     = NT / 32;            // n8 tiles per warp (8 or 4)
    constexpr int NP     = N8 / 2;             // ldmatrix B pairs
    constexpr int BBYTES = NT * 128;
    constexpr int STB    = ABYTES + BBYTES;
    extern __shared__ char dsmem[];
    __shared__ float red[128];

    const int tid  = threadIdx.x;
    const int warp = tid >> 5;
    const int lane = tid & 31;
    const int qid  = lane >> 2;
    const int kid  = lane & 3;
    const int wm   = (warp >> 2) * 64;
    const int wn   = (warp & 3) * (NT / 4);
    const int row0 = (swapgrid ? blockIdx.x : blockIdx.y) * 128;
    const int col0 = (swapgrid ? blockIdx.y : blockIdx.x) * NT;
    const int nch  = K / 64;                   // 64 halves per chunk
    const uint32_t sm0   = smem_u32(dsmem);
    const uint32_t data0 = (sm0 + 1023u) & ~1023u;

    // ldmatrix per-lane addressing (swizzle key: row & 7 == lane & 7 for A and B)
    const uint32_t swz = (uint32_t)(lane & 7) * 16;
    const int rA = lane & 15, cA = (lane >> 4) & 1;
    const int rB = lane & 7,  cB = (lane >> 3) & 1, whB = lane >> 4;
    uint32_t aoff[4], boff[NP];
#pragma unroll
    for (int mt = 0; mt < 4; mt++) aoff[mt] = (uint32_t)(wm + mt * 16 + rA) * 128;
#pragma unroll
    for (int p = 0; p < NP; p++)
        boff[p] = (uint32_t)ABYTES + (uint32_t)(wn + (2 * p + whB) * 8 + rB) * 128;

    float c[4][N8][4];
#pragma unroll
    for (int i = 0; i < 4; i++)
#pragma unroll
        for (int j = 0; j < N8; j++)
#pragma unroll
            for (int k = 0; k < 4; k++) c[i][j][k] = 0.f;

    auto load_chunk = [&](int ch, int s) {
        const int k0 = ch * 64;
        const uint32_t sa = data0 + (uint32_t)s * STB;
        const uint32_t sb = sa + ABYTES;
        const __half* Ag = A + (size_t)row0 * K + k0;
        const __half* Bg = B + (size_t)col0 * K + k0;
#pragma unroll
        for (int w = 0; w < 4; w++) {              // 128 rows x 8 x 16B
            int idx = tid + w * 256;
            int r = idx >> 3, c4 = idx & 7;
            uint32_t off = (uint32_t)r * 128 + (((uint32_t)c4 * 16) ^ (((uint32_t)r & 7) * 16));
            CP_ASYNC16(sa + off, Ag + (size_t)r * K + c4 * 8);
        }
#pragma unroll
        for (int w = 0; w < NT / 32; w++) {        // NT rows x 8 x 16B
            int idx = tid + w * 256;
            int r = idx >> 3, c4 = idx & 7;
            uint32_t off = (uint32_t)r * 128 + (((uint32_t)c4 * 16) ^ (((uint32_t)r & 7) * 16));
            CP_ASYNC16(sb + off, Bg + (size_t)r * K + c4 * 8);
        }
        CP_COMMIT();
    };

    for (int i = 0; i < STAGES; i++) load_chunk(i, i);

    for (int i = 0; i < nch; i++) {
        const int s = i % STAGES;
        CP_WAIT(STAGES - 1);
        __syncthreads();

        const uint32_t sAu = data0 + (uint32_t)s * STB;
#pragma unroll
        for (int k16 = 0; k16 < 4; k16++) {        // 4 x K=16 slabs per 64-half chunk
            const uint32_t offA = ((uint32_t)(k16 * 32 + cA * 16)) ^ swz;
            const uint32_t offB = ((uint32_t)(k16 * 32 + cB * 16)) ^ swz;
            uint32_t a[4][4], b[N8][2];
#pragma unroll
            for (int mt = 0; mt < 4; mt++)
                LDSM4(a[mt][0], a[mt][1], a[mt][2], a[mt][3], sAu + aoff[mt] + offA);
#pragma unroll
            for (int p = 0; p < NP; p++)
                LDSM4(b[2 * p][0], b[2 * p][1], b[2 * p + 1][0], b[2 * p + 1][1],
                      sAu + boff[p] + offB);
#pragma unroll
            for (int mt = 0; mt < 4; mt++)
#pragma unroll
                for (int nt = 0; nt < N8; nt++)
                    mma_f16(c[mt][nt], a[mt], b[nt]);
        }
        __syncthreads();
        if (i + STAGES < nch) load_chunk(i + STAGES, s);
        else                  CP_COMMIT();
    }

    // ---------------- epilogue ----------------
    if (mode == 2) {
        float bv[N8 * 2], wv[N8 * 2];
#pragma unroll
        for (int nt = 0; nt < N8; nt++)
#pragma unroll
            for (int j = 0; j < 2; j++) {
                int col = col0 + wn + nt * 8 + kid * 2 + j;
                bv[nt * 2 + j] = bias[col];
                wv[nt * 2 + j] = w2[col];
            }
        if (tid < 128) red[tid] = 0.f;
        __syncthreads();
#pragma unroll
        for (int mt = 0; mt < 4; mt++)
#pragma unroll
            for (int h = 0; h < 2; h++) {
                float part = 0.f;
#pragma unroll
                for (int nt = 0; nt < N8; nt++)
#pragma unroll
                    for (int j = 0; j < 2; j++) {
                        float v = c[mt][nt][h * 2 + j] + bv[nt * 2 + j];
                        part = fmaf(fmaxf(v, 0.f), wv[nt * 2 + j], part);
                    }
                part += __shfl_xor_sync(0xffffffffu, part, 1);
                part += __shfl_xor_sync(0xffffffffu, part, 2);
                if (kid == 0)
                    atomicAdd(&red[wm + mt * 16 + qid + h * 8], part);
            }
        __syncthreads();
        if (tid < 128) atomicAdd(&score[row0 + tid], red[tid]);
        return;
    }

#pragma unroll
    for (int mt = 0; mt < 4; mt++)
#pragma unroll
        for (int h = 0; h < 2; h++) {
            int row = row0 + wm + mt * 16 + qid + h * 8;
#pragma unroll
            for (int nt = 0; nt < N8; nt++) {
                float v0 = c[mt][nt][h * 2 + 0];
                float v1 = c[mt][nt][h * 2 + 1];
                int coll = col0 + wn + nt * 8 + kid * 2;
                if (mode == 1) {
                    v0 += bias[coll];
                    v1 += bias[coll + 1];
                    v0 = v0 >= 0.f ? v0 : 0.01f * v0;
                    v1 = v1 >= 0.f ? v1 : 0.01f * v1;
                    *(float2*)((float*)Cv + (size_t)row * Nc + coll) = make_float2(v0, v1);
                } else {
                    *(__half2*)((__half*)Cv + (size_t)row * Nc + coll) =
                        __floats2half2_rn(v0, v1);
                }
            }
        }
}

// ---------------- fp16 pre-conversion ----------------
__global__ void k_cvt_h(const float4* __restrict__ src, __half2* __restrict__ dst, int n4) {
    int i = blockIdx.x * blockDim.x + threadIdx.x;
    if (i >= n4) return;
    float4 v = src[i];
    dst[2 * i]     = __floats2half2_rn(v.x, v.y);
    dst[2 * i + 1] = __floats2half2_rn(v.z, v.w);
}

// ---------------- wv = W^T @ att[F:]  (et GEMM eliminated) ----------------
__global__ void k_watt(const float* __restrict__ W, const float* __restrict__ att) {
    int k = blockIdx.x * blockDim.x + threadIdx.x;
    if (k >= F) return;
    float s = 0.f;
    for (int f = 0; f < F; f++) s = fmaf(W[f * F + k], att[F + f], s);
    g_wv[k] = s;
}

// ---------------- CSR build (once) ----------------
__global__ void k_csr_zero() {
    int i = blockIdx.x * blockDim.x + threadIdx.x;
    if (i < NN) { g_cnt_c[i] = 0; g_cnt_r[i] = 0; g_cur_c[i] = 0; g_cur_r[i] = 0; }
}
__global__ void k_csr_count(const int* __restrict__ ei) {
    int e = blockIdx.x * blockDim.x + threadIdx.x;
    if (e >= NNZ) return;
    atomicAdd(&g_cnt_c[ei[NNZ + e]], 1);
    atomicAdd(&g_cnt_r[ei[e]], 1);
}
__global__ void k_scan2() {
    __shared__ int part[1024];
    const int* cnt = blockIdx.x ? g_cnt_r : g_cnt_c;
    int*       off = blockIdx.x ? g_off_r : g_off_c;
    int t = threadIdx.x;
    int loc[8];
    int s = 0;
#pragma unroll
    for (int i = 0; i < 8; i++) { loc[i] = s; s += cnt[t * 8 + i]; }
    part[t] = s;
    __syncthreads();
    for (int d = 1; d < 1024; d <<= 1) {
        int v = (t >= d) ? part[t - d] : 0;
        __syncthreads();
        part[t] += v;
        __syncthreads();
    }
    int base = (t == 0) ? 0 : part[t - 1];
#pragma unroll
    for (int i = 0; i < 8; i++) off[t * 8 + i] = base + loc[i];
    if (t == 1023) off[NN] = part[1023];
}
__global__ void k_csr_place(const int* __restrict__ ei) {
    int e = blockIdx.x * blockDim.x + threadIdx.x;
    if (e >= NNZ) return;
    int r = ei[e], c = ei[NNZ + e];
    int pc = atomicAdd(&g_cur_c[c], 1);
    g_perm_c[g_off_c[c] + pc] = e;
    int pr = atomicAdd(&g_cur_r[r], 1);
    g_perm_r[g_off_r[r] + pr] = e;
}

// ---------------- small utility kernels ----------------
__global__ void k_zero_gn() {
    int c = threadIdx.x;
    if (c < F) { g_colsum[c] = 0.f; g_colsq[c] = 0.f; }
}
__global__ void k_zero_score() {
    int d = blockIdx.x * blockDim.x + threadIdx.x;
    if (d < DCAT) g_score[d] = 0.f;
}

// ---------------- GraphNorm ----------------
__global__ void k_gn_reduce(const float* __restrict__ X) {
    int c  = threadIdx.x;
    int r0 = blockIdx.x * 64;
    float s = 0.f, q = 0.f;
    for (int i = 0; i < 64; i++) {
        float v = X[(size_t)(r0 + i) * F + c];
        s += v;
        q += v * v;
    }
    atomicAdd(&g_colsum[c], s);
    atomicAdd(&g_colsq[c], q);
}

__global__ void k_gn_apply(const float* __restrict__ X,
                           const float* __restrict__ w,
                           const float* __restrict__ b,
                           const float* __restrict__ ms) {
    int idx = blockIdx.x * blockDim.x + threadIdx.x;
    if (idx >= NN * F) return;
    int c = idx % F;
    float invN  = 1.f / (float)NN;
    float mean  = g_colsum[c] * invN;
    float m     = ms[c];
    float var   = g_colsq[c] * invN - m * (2.f - m) * mean * mean;
    float outv  = X[idx] - m * mean;
    g_xn16[idx] = __float2half_rn(w[c] * outv * rsqrtf(var + 1e-5f) + b[c]);
}

// ---------------- ax = xt@att[:F] (fp16 xt), ae = eattr@wv ----------------
__global__ void k_gemv_att(const float* __restrict__ att, const float* __restrict__ eattr) {
    int w    = (blockIdx.x * blockDim.x + threadIdx.x) >> 5;
    int lane = threadIdx.x & 31;
    if (w >= NN) return;
    const __half* xr = g_xt16 + (size_t)w * F;
    const float*  er = eattr + (size_t)w * F;
    float s1 = 0.f, s2 = 0.f;
    for (int i = lane * 2; i < F; i += 64) {
        float2 v = __half22float2(*(const __half2*)&xr[i]);
        s1 = fmaf(v.x, att[i],     s1);
        s1 = fmaf(v.y, att[i + 1], s1);
    }
    for (int i = lane; i < F; i += 32) s2 = fmaf(er[i], g_wv[i], s2);
#pragma unroll
    for (int off = 16; off; off >>= 1) {
        s1 += __shfl_xor_sync(0xffffffffu, s1, off);
        s2 += __shfl_xor_sync(0xffffffffu, s2, off);
    }
    if (lane == 0) { g_ax[w] = s1; g_ae[w] = s2; }
}

// ---------------- fused per-hyperedge softmax (warp per segment) ----------------
__global__ void k_seg_softmax(const int* __restrict__ ei) {
    int w    = (blockIdx.x * blockDim.x + threadIdx.x) >> 5;
    int lane = threadIdx.x & 31;
    if (w >= NN) return;
    int s = g_off_c[w], n = g_off_c[w + 1] - s;
    if (n == 0) return;
    float aec = g_ae[w];
    float m = -3.4e38f;
    for (int i = lane; i < n; i += 32) {
        int e = g_perm_c[s + i];
        float a = g_ax[ei[e]] + aec;
        a = a >= 0.f ? a : 0.2f * a;
        g_alpha[e] = a;
        m = fmaxf(m, a);
    }
#pragma unroll
    for (int o = 16; o; o >>= 1) m = fmaxf(m, __shfl_xor_sync(0xffffffffu, m, o));
    float sum = 0.f;
    for (int i = lane; i < n; i += 32) {
        int e = g_perm_c[s + i];
        float ex = expf(g_alpha[e] - m);
        g_alpha[e] = ex;
        sum += ex;
    }
#pragma unroll
    for (int o = 16; o; o >>= 1) sum += __shfl_xor_sync(0xffffffffu, sum, o);
    float inv = 1.f / (sum + 1e-16f);
    for (int i = lane; i < n; i += 32) g_alpha[g_perm_c[s + i]] *= inv;
}

// ---------------- atomic-free scatters: block per segment, fp16 gather sources ----------------
#define SCH 64
__global__ void k_scatter_e(const int* __restrict__ ei) {   // node -> hyperedge
    __shared__ float scoef[SCH];
    __shared__ int   sidx[SCH];
    int c = blockIdx.x;
    int s = g_off_c[c], end = g_off_c[c + 1];
    int n = end - s;
    float bn = n > 0 ? 1.f / (float)n : 0.f;
    int f = threadIdx.x * 4;
    float4 acc = make_float4(0.f, 0.f, 0.f, 0.f);
    while (s < end) {
        int chunk = min(SCH, end - s);
        __syncthreads();
        if ((int)threadIdx.x < chunk) {
            int e = g_perm_c[s + threadIdx.x];
            scoef[threadIdx.x] = bn * g_alpha[e];
            sidx[threadIdx.x]  = ei[e];                 // row
        }
        __syncthreads();
        for (int j = 0; j < chunk; j++) {
            float cf = scoef[j];
            uint2 u = *(const uint2*)&g_xt16[(size_t)sidx[j] * F + f];
            float2 v0 = __half22float2(*(__half2*)&u.x);
            float2 v1 = __half22float2(*(__half2*)&u.y);
            acc.x = fmaf(cf, v0.x, acc.x);
            acc.y = fmaf(cf, v0.y, acc.y);
            acc.z = fmaf(cf, v1.x, acc.z);
            acc.w = fmaf(cf, v1.y, acc.w);
        }
        s += chunk;
    }
    uint2 o;
    *(__half2*)&o.x = __floats2half2_rn(acc.x, acc.y);
    *(__half2*)&o.y = __floats2half2_rn(acc.z, acc.w);
    *(uint2*)&g_ef16[(size_t)c * F + f] = o;
}

__global__ void k_scatter_n(const int* __restrict__ ei, const float* __restrict__ bias) {
    __shared__ float scoef[SCH];
    __shared__ int   sidx[SCH];
    int r = blockIdx.x;
    int s = g_off_r[r], end = g_off_r[r + 1];
    int n = end - s;
    float dn = n > 0 ? 1.f / (float)n : 0.f;
    int f = threadIdx.x * 4;
    float4 acc = make_float4(0.f, 0.f, 0.f, 0.f);
    while (s < end) {
        int chunk = min(SCH, end - s);
        __syncthreads();
        if ((int)threadIdx.x < chunk) {
            int e = g_perm_r[s + threadIdx.x];
            scoef[threadIdx.x] = dn * g_alpha[e];
            sidx[threadIdx.x]  = ei[NNZ + e];           // col
        }
        __syncthreads();
        for (int j = 0; j < chunk; j++) {
            float cf = scoef[j];
            uint2 u = *(const uint2*)&g_ef16[(size_t)sidx[j] * F + f];
            float2 v0 = __half22float2(*(__half2*)&u.x);
            float2 v1 = __half22float2(*(__half2*)&u.y);
            acc.x = fmaf(cf, v0.x, acc.x);
            acc.y = fmaf(cf, v0.y, acc.y);
            acc.z = fmaf(cf, v1.x, acc.z);
            acc.w = fmaf(cf, v1.y, acc.w);
        }
        s += chunk;
    }
    // fused: + bias, leaky relu 0.01; write fp32 (GN input) and fp16 (GEMM input)
    float4 b4 = *(const float4*)&bias[f];
    acc.x += b4.x; acc.y += b4.y; acc.z += b4.z; acc.w += b4.w;
    acc.x = acc.x >= 0.f ? acc.x : 0.01f * acc.x;
    acc.y = acc.y >= 0.f ? acc.y : 0.01f * acc.y;
    acc.z = acc.z >= 0.f ? acc.z : 0.01f * acc.z;
    acc.w = acc.w >= 0.f ? acc.w : 0.01f * acc.w;
    *(float4*)&g_h[(size_t)r * F + f] = acc;
    __half2* hp = (__half2*)&g_h16[(size_t)r * F + f];
    hp[0] = __floats2half2_rn(acc.x, acc.y);
    hp[1] = __floats2half2_rn(acc.z, acc.w);
}

// ---------------- transpose src[NN,C] -> fp16 dst[c*NN + r] ----------------
__global__ void k_transpose(const float* __restrict__ src, int C, __half* __restrict__ dst) {
    __shared__ float t[32][33];
    int c0 = blockIdx.x * 32, r0 = blockIdx.y * 32;
    int tx = threadIdx.x, ty = threadIdx.y;
#pragma unroll
    for (int i = 0; i < 4; i++)
        t[ty + 8 * i][tx] = src[(size_t)(r0 + ty + 8 * i) * C + c0 + tx];
    __syncthreads();
#pragma unroll
    for (int i = 0; i < 4; i++)
        dst[(size_t)(c0 + ty + 8 * i) * NN + r0 + tx] = __float2half_rn(t[tx][ty + 8 * i]);
}

// ---------------- score finalize + folded classifier ----------------
__global__ void k_score_final(const float* __restrict__ b2, const float* __restrict__ center) {
    int d = blockIdx.x * blockDim.x + threadIdx.x;
    if (d >= DCAT) return;
    float r = g_score[d] + b2[0];
    float sg = 1.f / (1.f + expf(-r));
    g_score[d] = sg - center[d];
}

__global__ void k_wp(const float* __restrict__ clsW) {
    int idx = blockIdx.x * blockDim.x + threadIdx.x;
    if (idx >= OUTD * DCAT) return;
    g_wp[idx] = clsW[idx] * g_score[idx % DCAT];
}

__global__ void k_logits(const float* __restrict__ x, const float* __restrict__ clsb,
                         float* __restrict__ out) {
    int n    = (blockIdx.x * blockDim.x + threadIdx.x) >> 5;
    int lane = threadIdx.x & 31;
    if (n >= NN) return;
    float acc[OUTD];
#pragma unroll
    for (int o = 0; o < OUTD; o++) acc[o] = 0.f;

    const float* xr = x + (size_t)n * F;
#pragma unroll
    for (int it = 0; it < 6; it++) {
        int i = lane * 4 + it * 128;
        float4 v = *(const float4*)&xr[i];
#pragma unroll
        for (int o = 0; o < OUTD; o++) {
            float4 w = *(const float4*)&g_wp[o * DCAT + i];
            acc[o] += v.x * w.x + v.y * w.y + v.z * w.z + v.w * w.w;
        }
    }
    const float* o1 = g_out1 + (size_t)n * HIDD;
#pragma unroll
    for (int it = 0; it < 3; it++) {
        int i = lane * 4 + it * 128;
        float4 v = *(const float4*)&o1[i];
#pragma unroll
        for (int o = 0; o < OUTD; o++) {
            float4 w = *(const float4*)&g_wp[o * DCAT + F + i];
            acc[o] += v.x * w.x + v.y * w.y + v.z * w.z + v.w * w.w;
        }
    }
    const float* o2 = g_out2 + (size_t)n * HIDD;
#pragma unroll
    for (int it = 0; it < 3; it++) {
        int i = lane * 4 + it * 128;
        float4 v = *(const float4*)&o2[i];
#pragma unroll
        for (int o = 0; o < OUTD; o++) {
            float4 w = *(const float4*)&g_wp[o * DCAT + F + HIDD + i];
            acc[o] += v.x * w.x + v.y * w.y + v.z * w.z + v.w * w.w;
        }
    }
#pragma unroll
    for (int o = 0; o < OUTD; o++) {
        float v = acc[o];
#pragma unroll
        for (int off = 16; off; off >>= 1) v += __shfl_xor_sync(0xffffffffu, v, off);
        if (lane == 0) out[(size_t)n * OUTD + o] = v + clsb[o];
    }
}

// ---------------- host-side driver ----------------
static const int SMEM256 = STAGES * (ABYTES + 256 * 128) + 1024;  // 148480
static const int SMEM128 = STAGES * (ABYTES + 128 * 128) + 1024;  //  99328

static void run_conv(const float* feat_in, const int* ei, const float* eattr,
                     const float* gw, const float* gb, const float* gms,
                     const float* W, const float* att, const float* hb,
                     __half* p_xn16, __half* p_wh, __half* p_xt16)
{
    k_zero_gn<<<1, 768>>>();
    k_gn_reduce<<<NN / 64, 768>>>(feat_in);
    k_gn_apply<<<NN * F / 256, 256>>>(feat_in, gw, gb, gms);
    k_cvt_h<<<(F * F / 4 + 255) / 256, 256>>>((const float4*)W, (__half2*)p_wh, F * F / 4);
    k_watt<<<(F + 255) / 256, 256>>>(W, att);
    k_gemm<256><<<dim3(F / 256, NN / 128), 256, SMEM256>>>(
        p_xn16, p_wh, p_xt16, F, F, 0, 0, nullptr, nullptr, nullptr);
    k_gemv_att<<<NN / 8, 256>>>(att, eattr);
    k_seg_softmax<<<NN / 8, 256>>>(ei);
    k_scatter_e<<<NN, 192>>>(ei);
    k_scatter_n<<<NN, 192>>>(ei, hb);
}

extern "C" void kernel_launch(void* const* d_in, const int* in_sizes, int n_in,
                              void* d_out, int out_size) {
    const float* x       = (const float*)d_in[0];
    const int*   ei      = (const int*)  d_in[1];
    const float* eattr   = (const float*)d_in[2];
    const float* gn1_w   = (const float*)d_in[3];
    const float* gn1_b   = (const float*)d_in[4];
    const float* gn1_ms  = (const float*)d_in[5];
    const float* gn2_w   = (const float*)d_in[6];
    const float* gn2_b   = (const float*)d_in[7];
    const float* gn2_ms  = (const float*)d_in[8];
    const float* hg1_W   = (const float*)d_in[9];
    const float* hg1_att = (const float*)d_in[10];
    const float* hg1_b   = (const float*)d_in[11];
    const float* hg2_W   = (const float*)d_in[12];
    const float* hg2_att = (const float*)d_in[13];
    const float* hg2_b   = (const float*)d_in[14];
    const float* fc1_W   = (const float*)d_in[15];
    const float* fc1_b   = (const float*)d_in[16];
    const float* fc2_W   = (const float*)d_in[17];
    const float* fc2_b   = (const float*)d_in[18];
    const float* attn_W1 = (const float*)d_in[19];
    const float* attn_b1 = (const float*)d_in[20];
    const float* attn_W2 = (const float*)d_in[21];
    const float* attn_b2 = (const float*)d_in[22];
    const float* cls_W   = (const float*)d_in[23];
    const float* cls_b   = (const float*)d_in[24];
    const float* center  = (const float*)d_in[25];
    float*       out     = (float*)d_out;

    cudaFuncSetAttribute(k_gemm<256>, cudaFuncAttributeMaxDynamicSharedMemorySize, SMEM256);
    cudaFuncSetAttribute(k_gemm<128>, cudaFuncAttributeMaxDynamicSharedMemorySize, SMEM128);

    float *p_h, *p_out1, *p_out2, *p_score;
    __half *p_xn16, *p_xt16, *p_h16, *p_catT16, *p_w1h, *p_wh, *p_fwh;
    cudaGetSymbolAddress((void**)&p_h,       g_h);
    cudaGetSymbolAddress((void**)&p_out1,    g_out1);
    cudaGetSymbolAddress((void**)&p_out2,    g_out2);
    cudaGetSymbolAddress((void**)&p_score,   g_score);
    cudaGetSymbolAddress((void**)&p_xn16,    g_xn16);
    cudaGetSymbolAddress((void**)&p_xt16,    g_xt16);
    cudaGetSymbolAddress((void**)&p_h16,     g_h16);
    cudaGetSymbolAddress((void**)&p_catT16,  g_catT16);
    cudaGetSymbolAddress((void**)&p_w1h,     g_w1h);
    cudaGetSymbolAddress((void**)&p_wh,      g_wh);
    cudaGetSymbolAddress((void**)&p_fwh,     g_fwh);

    // ---- CSR build (once) + big one-time fp16 conversion ----
    k_csr_zero<<<NN / 256, 256>>>();
    k_csr_count<<<NNZ / 256, 256>>>(ei);
    k_scan2<<<2, 1024>>>();
    k_csr_place<<<NNZ / 256, 256>>>(ei);
    k_cvt_h<<<(int)((size_t)NN * NN / 4 / 256), 256>>>((const float4*)attn_W1, (__half2*)p_w1h,
                                                       (int)((size_t)NN * NN / 4));

    // ---- conv1 + fc1 ----
    run_conv(x, ei, eattr, gn1_w, gn1_b, gn1_ms, hg1_W, hg1_att, hg1_b, p_xn16, p_wh, p_xt16);
    k_cvt_h<<<(HIDD * F / 4 + 255) / 256, 256>>>((const float4*)fc1_W, (__half2*)p_fwh, HIDD * F / 4);
    k_gemm<128><<<dim3(HIDD / 128, NN / 128), 256, SMEM128>>>(
        p_h16, p_fwh, p_out1, HIDD, F, 1, 0, fc1_b, nullptr, nullptr);

    // ---- conv2 (graphnorm reads fp32 g_h = h1 before scatter_n overwrites it) + fc2 ----
    run_conv(p_h, ei, eattr, gn2_w, gn2_b, gn2_ms, hg2_W, hg2_att, hg2_b, p_xn16, p_wh, p_xt16);
    k_cvt_h<<<(HIDD * F / 4 + 255) / 256, 256>>>((const float4*)fc2_W, (__half2*)p_fwh, HIDD * F / 4);
    k_gemm<128><<<dim3(HIDD / 128, NN / 128), 256, SMEM128>>>(
        p_h16, p_fwh, p_out2, HIDD, F, 1, 0, fc2_b, nullptr, nullptr);

    // ---- catT = [x; out1; out2]^T in fp16 (node-contiguous) ----
    k_transpose<<<dim3(F / 32,    NN / 32), dim3(32, 8)>>>(x,      F,    p_catT16);
    k_transpose<<<dim3(HIDD / 32, NN / 32), dim3(32, 8)>>>(p_out1, HIDD, p_catT16 + (size_t)F * NN);
    k_transpose<<<dim3(HIDD / 32, NN / 32), dim3(32, 8)>>>(p_out2, HIDD, p_catT16 + (size_t)(F + HIDD) * NN);

    // ---- attention: score[d] = sum_j relu(catT@W1^T + b1)[d,j] * W2[j] ----
    // swapped grid: row tiles fastest -> consecutive CTAs share the same W1 panel (L2 reuse)
    k_zero_score<<<(DCAT + 255) / 256, 256>>>();
    k_gemm<256><<<dim3(DCAT / 128, NN / 256), 256, SMEM256>>>(
        p_catT16, p_w1h, nullptr, NN, NN, 2, 1, attn_b1, attn_W2, p_score);
    k_score_final<<<(DCAT + 255) / 256, 256>>>(attn_b2, center);

    // ---- classifier with score folded into weights ----
    k_wp<<<(OUTD * DCAT + 255) / 256, 256>>>(cls_W);
    k_logits<<<NN * 32 / 256, 256>>>(x, cls_b, out);
}

// round 15
// speedup vs baseline: 1.0583x; 1.0373x over previous
#include <cuda_runtime.h>
#include <cuda_fp16.h>
#include <cstdint>

#define NN   8192
#define F    768
#define HIDD 384
#define OUTD 10
#define NNZ  (NN * 16)
#define DCAT (F + 2 * HIDD)

#define STAGES  3
#define ABYTES  (128 * 128)        // A tile: 128 rows x 128 B (= 64 halves/row)

// ---------------- scratch (device globals; no allocation allowed) ----------------
__device__ __align__(16) __half g_xn16[NN * F];
__device__ __align__(16) __half g_xt16[NN * F];
__device__ __align__(16) __half g_ef16[NN * F];
__device__ __align__(16) float  g_h[NN * F];
__device__ __align__(16) __half g_h16[NN * F];
__device__ __align__(16) float  g_out1[NN * HIDD];
__device__ __align__(16) float  g_out2[NN * HIDD];
__device__ __align__(16) __half g_catT16[(size_t)DCAT * NN];
__device__ __align__(16) __half g_w1h[(size_t)NN * NN];   // attn_W1 fp16
__device__ __align__(16) __half g_wh[F * F];              // hg W fp16
__device__ __align__(16) __half g_fwh[HIDD * F];          // fc W fp16
__device__ float    g_alpha[NNZ];
__device__ float    g_ax[NN];
__device__ float    g_ae[NN];
__device__ float    g_wv[F];          // W^T @ att[F:]
__device__ float    g_score[DCAT];
__device__ float    g_wp[OUTD * DCAT];
__device__ float    g_colsum[F];
__device__ float    g_colsq[F];
// CSR structures (built once; edge_index identical for both convs)
__device__ int      g_cnt_c[NN], g_cnt_r[NN];
__device__ int      g_cur_c[NN], g_cur_r[NN];
__device__ int      g_off_c[NN + 1], g_off_r[NN + 1];
__device__ int      g_perm_c[NNZ], g_perm_r[NNZ];

// ---------------- PTX helpers (plain sm_103-safe, sm_80 features) ----------------
__device__ __forceinline__ uint32_t smem_u32(const void* p) {
    uint32_t a;
    asm("{ .reg .u64 t; cvta.to.shared.u64 t, %1; cvt.u32.u64 %0, t; }" : "=r"(a) : "l"(p));
    return a;
}
#define CP_ASYNC16(d, s) \
    asm volatile("cp.async.cg.shared.global [%0], [%1], 16;" :: "r"(d), "l"(s) : "memory")
#define CP_COMMIT()      asm volatile("cp.async.commit_group;" ::: "memory")
#define CP_WAIT(n)       asm volatile("cp.async.wait_group %0;" :: "n"(n) : "memory")

#define LDSM4(r0, r1, r2, r3, addr) \
    asm volatile("ldmatrix.sync.aligned.m8n8.x4.shared.b16 {%0,%1,%2,%3}, [%4];" \
                 : "=r"(r0), "=r"(r1), "=r"(r2), "=r"(r3) : "r"(addr))

__device__ __forceinline__ void mma_f16(float* c, const uint32_t* a, const uint32_t* b) {
    asm volatile(
        "mma.sync.aligned.m16n8k16.row.col.f32.f16.f16.f32 "
        "{%0,%1,%2,%3}, {%4,%5,%6,%7}, {%8,%9}, {%0,%1,%2,%3};"
        : "+f"(c[0]), "+f"(c[1]), "+f"(c[2]), "+f"(c[3])
        : "r"(a[0]), "r"(a[1]), "r"(a[2]), "r"(a[3]), "r"(b[0]), "r"(b[1]));
}

// ---------------- fp16 mma.sync NT GEMM: C[M,Nc] = A[M,K] * B[Nc,K]^T ----------------
// CTA tile 128 x 128 (2 CTAs/SM: 97 KB smem, <=128 regs), 8 warps (2M x 4N),
// warp tile 64 x 32. K-chunk = 64 halves. ldmatrix.x4 fragment loads.
// swapgrid=1: row tiles on blockIdx.x (consecutive CTAs share B panel -> L2 reuse).
// mode 0: store C fp16. mode 1: C fp32 = lrelu(acc + bias[col], 0.01).
// mode 2: no C; score[row] += sum_col relu(acc + bias[col]) * w2[col].
__global__ void __launch_bounds__(256, 2) k_gemm(
    const __half* __restrict__ A, const __half* __restrict__ B, void* __restrict__ Cv,
    int Nc, int K, int mode, int swapgrid,
    const float* __restrict__ bias, const float* __restrict__ w2,
    float* __restrict__ score)
{
    constexpr int NT     = 128;
    constexpr int N8     = NT / 32;            // 4 n8 tiles per warp
    constexpr int NP     = N8 / 2;             // 2 ldmatrix B pairs
    constexpr int BBYTES = NT * 128;
    constexpr int STB    = ABYTES + BBYTES;
    extern __shared__ char dsmem[];
    __shared__ float red[128];

    const int tid  = threadIdx.x;
    const int warp = tid >> 5;
    const int lane = tid & 31;
    const int qid  = lane >> 2;
    const int kid  = lane & 3;
    const int wm   = (warp >> 2) * 64;
    const int wn   = (warp & 3) * (NT / 4);
    const int row0 = (swapgrid ? blockIdx.x : blockIdx.y) * 128;
    const int col0 = (swapgrid ? blockIdx.y : blockIdx.x) * NT;
    const int nch  = K / 64;                   // 64 halves per chunk
    const uint32_t sm0   = smem_u32(dsmem);
    const uint32_t data0 = (sm0 + 1023u) & ~1023u;

    // ldmatrix per-lane addressing (swizzle key: row & 7 == lane & 7 for A and B)
    const uint32_t swz = (uint32_t)(lane & 7) * 16;
    const int rA = lane & 15, cA = (lane >> 4) & 1;
    const int rB = lane & 7,  cB = (lane >> 3) & 1, whB = lane >> 4;
    uint32_t aoff[4], boff[NP];
#pragma unroll
    for (int mt = 0; mt < 4; mt++) aoff[mt] = (uint32_t)(wm + mt * 16 + rA) * 128;
#pragma unroll
    for (int p = 0; p < NP; p++)
        boff[p] = (uint32_t)ABYTES + (uint32_t)(wn + (2 * p + whB) * 8 + rB) * 128;

    float c[4][N8][4];
#pragma unroll
    for (int i = 0; i < 4; i++)
#pragma unroll
        for (int j = 0; j < N8; j++)
#pragma unroll
            for (int k = 0; k < 4; k++) c[i][j][k] = 0.f;

    auto load_chunk = [&](int ch, int s) {
        const int k0 = ch * 64;
        const uint32_t sa = data0 + (uint32_t)s * STB;
        const uint32_t sb = sa + ABYTES;
        const __half* Ag = A + (size_t)row0 * K + k0;
        const __half* Bg = B + (size_t)col0 * K + k0;
#pragma unroll
        for (int w = 0; w < 4; w++) {              // 128 rows x 8 x 16B
            int idx = tid + w * 256;
            int r = idx >> 3, c4 = idx & 7;
            uint32_t off = (uint32_t)r * 128 + (((uint32_t)c4 * 16) ^ (((uint32_t)r & 7) * 16));
            CP_ASYNC16(sa + off, Ag + (size_t)r * K + c4 * 8);
        }
#pragma unroll
        for (int w = 0; w < NT / 32; w++) {        // NT rows x 8 x 16B
            int idx = tid + w * 256;
            int r = idx >> 3, c4 = idx & 7;
            uint32_t off = (uint32_t)r * 128 + (((uint32_t)c4 * 16) ^ (((uint32_t)r & 7) * 16));
            CP_ASYNC16(sb + off, Bg + (size_t)r * K + c4 * 8);
        }
        CP_COMMIT();
    };

    for (int i = 0; i < STAGES; i++) load_chunk(i, i);

    for (int i = 0; i < nch; i++) {
        const int s = i % STAGES;
        CP_WAIT(STAGES - 1);
        __syncthreads();

        const uint32_t sAu = data0 + (uint32_t)s * STB;
#pragma unroll
        for (int k16 = 0; k16 < 4; k16++) {        // 4 x K=16 slabs per 64-half chunk
            const uint32_t offA = ((uint32_t)(k16 * 32 + cA * 16)) ^ swz;
            const uint32_t offB = ((uint32_t)(k16 * 32 + cB * 16)) ^ swz;
            uint32_t a[4][4], b[N8][2];
#pragma unroll
            for (int mt = 0; mt < 4; mt++)
                LDSM4(a[mt][0], a[mt][1], a[mt][2], a[mt][3], sAu + aoff[mt] + offA);
#pragma unroll
            for (int p = 0; p < NP; p++)
                LDSM4(b[2 * p][0], b[2 * p][1], b[2 * p + 1][0], b[2 * p + 1][1],
                      sAu + boff[p] + offB);
#pragma unroll
            for (int mt = 0; mt < 4; mt++)
#pragma unroll
                for (int nt = 0; nt < N8; nt++)
                    mma_f16(c[mt][nt], a[mt], b[nt]);
        }
        __syncthreads();
        if (i + STAGES < nch) load_chunk(i + STAGES, s);
        else                  CP_COMMIT();
    }

    // ---------------- epilogue ----------------
    if (mode == 2) {
        float bv[N8 * 2], wv[N8 * 2];
#pragma unroll
        for (int nt = 0; nt < N8; nt++)
#pragma unroll
            for (int j = 0; j < 2; j++) {
                int col = col0 + wn + nt * 8 + kid * 2 + j;
                bv[nt * 2 + j] = bias[col];
                wv[nt * 2 + j] = w2[col];
            }
        if (tid < 128) red[tid] = 0.f;
        __syncthreads();
#pragma unroll
        for (int mt = 0; mt < 4; mt++)
#pragma unroll
            for (int h = 0; h < 2; h++) {
                float part = 0.f;
#pragma unroll
                for (int nt = 0; nt < N8; nt++)
#pragma unroll
                    for (int j = 0; j < 2; j++) {
                        float v = c[mt][nt][h * 2 + j] + bv[nt * 2 + j];
                        part = fmaf(fmaxf(v, 0.f), wv[nt * 2 + j], part);
                    }
                part += __shfl_xor_sync(0xffffffffu, part, 1);
                part += __shfl_xor_sync(0xffffffffu, part, 2);
                if (kid == 0)
                    atomicAdd(&red[wm + mt * 16 + qid + h * 8], part);
            }
        __syncthreads();
        if (tid < 128) atomicAdd(&score[row0 + tid], red[tid]);
        return;
    }

#pragma unroll
    for (int mt = 0; mt < 4; mt++)
#pragma unroll
        for (int h = 0; h < 2; h++) {
            int row = row0 + wm + mt * 16 + qid + h * 8;
#pragma unroll
            for (int nt = 0; nt < N8; nt++) {
                float v0 = c[mt][nt][h * 2 + 0];
                float v1 = c[mt][nt][h * 2 + 1];
                int coll = col0 + wn + nt * 8 + kid * 2;
                if (mode == 1) {
                    v0 += bias[coll];
                    v1 += bias[coll + 1];
                    v0 = v0 >= 0.f ? v0 : 0.01f * v0;
                    v1 = v1 >= 0.f ? v1 : 0.01f * v1;
                    *(float2*)((float*)Cv + (size_t)row * Nc + coll) = make_float2(v0, v1);
                } else {
                    *(__half2*)((__half*)Cv + (size_t)row * Nc + coll) =
                        __floats2half2_rn(v0, v1);
                }
            }
        }
}

// ---------------- fp16 pre-conversion ----------------
__global__ void k_cvt_h(const float4* __restrict__ src, __half2* __restrict__ dst, int n4) {
    int i = blockIdx.x * blockDim.x + threadIdx.x;
    if (i >= n4) return;
    float4 v = src[i];
    dst[2 * i]     = __floats2half2_rn(v.x, v.y);
    dst[2 * i + 1] = __floats2half2_rn(v.z, v.w);
}

// ---------------- wv = W^T @ att[F:]  (et GEMM eliminated) ----------------
__global__ void k_watt(const float* __restrict__ W, const float* __restrict__ att) {
    int k = blockIdx.x * blockDim.x + threadIdx.x;
    if (k >= F) return;
    float s = 0.f;
    for (int f = 0; f < F; f++) s = fmaf(W[f * F + k], att[F + f], s);
    g_wv[k] = s;
}

// ---------------- CSR build (once) ----------------
__global__ void k_csr_zero() {
    int i = blockIdx.x * blockDim.x + threadIdx.x;
    if (i < NN) { g_cnt_c[i] = 0; g_cnt_r[i] = 0; g_cur_c[i] = 0; g_cur_r[i] = 0; }
}
__global__ void k_csr_count(const int* __restrict__ ei) {
    int e = blockIdx.x * blockDim.x + threadIdx.x;
    if (e >= NNZ) return;
    atomicAdd(&g_cnt_c[ei[NNZ + e]], 1);
    atomicAdd(&g_cnt_r[ei[e]], 1);
}
__global__ void k_scan2() {
    __shared__ int part[1024];
    const int* cnt = blockIdx.x ? g_cnt_r : g_cnt_c;
    int*       off = blockIdx.x ? g_off_r : g_off_c;
    int t = threadIdx.x;
    int loc[8];
    int s = 0;
#pragma unroll
    for (int i = 0; i < 8; i++) { loc[i] = s; s += cnt[t * 8 + i]; }
    part[t] = s;
    __syncthreads();
    for (int d = 1; d < 1024; d <<= 1) {
        int v = (t >= d) ? part[t - d] : 0;
        __syncthreads();
        part[t] += v;
        __syncthreads();
    }
    int base = (t == 0) ? 0 : part[t - 1];
#pragma unroll
    for (int i = 0; i < 8; i++) off[t * 8 + i] = base + loc[i];
    if (t == 1023) off[NN] = part[1023];
}
__global__ void k_csr_place(const int* __restrict__ ei) {
    int e = blockIdx.x * blockDim.x + threadIdx.x;
    if (e >= NNZ) return;
    int r = ei[e], c = ei[NNZ + e];
    int pc = atomicAdd(&g_cur_c[c], 1);
    g_perm_c[g_off_c[c] + pc] = e;
    int pr = atomicAdd(&g_cur_r[r], 1);
    g_perm_r[g_off_r[r] + pr] = e;
}

// ---------------- small utility kernels ----------------
__global__ void k_zero_gn() {
    int c = threadIdx.x;
    if (c < F) { g_colsum[c] = 0.f; g_colsq[c] = 0.f; }
}
__global__ void k_zero_score() {
    int d = blockIdx.x * blockDim.x + threadIdx.x;
    if (d < DCAT) g_score[d] = 0.f;
}

// ---------------- GraphNorm ----------------
__global__ void k_gn_reduce(const float* __restrict__ X) {
    int c  = threadIdx.x;
    int r0 = blockIdx.x * 64;
    float s = 0.f, q = 0.f;
    for (int i = 0; i < 64; i++) {
        float v = X[(size_t)(r0 + i) * F + c];
        s += v;
        q += v * v;
    }
    atomicAdd(&g_colsum[c], s);
    atomicAdd(&g_colsq[c], q);
}

__global__ void k_gn_apply(const float* __restrict__ X,
                           const float* __restrict__ w,
                           const float* __restrict__ b,
                           const float* __restrict__ ms) {
    int idx = blockIdx.x * blockDim.x + threadIdx.x;
    if (idx >= NN * F) return;
    int c = idx % F;
    float invN  = 1.f / (float)NN;
    float mean  = g_colsum[c] * invN;
    float m     = ms[c];
    float var   = g_colsq[c] * invN - m * (2.f - m) * mean * mean;
    float outv  = X[idx] - m * mean;
    g_xn16[idx] = __float2half_rn(w[c] * outv * rsqrtf(var + 1e-5f) + b[c]);
}

// ---------------- ax = xt@att[:F] (fp16 xt), ae = eattr@wv ----------------
__global__ void k_gemv_att(const float* __restrict__ att, const float* __restrict__ eattr) {
    int w    = (blockIdx.x * blockDim.x + threadIdx.x) >> 5;
    int lane = threadIdx.x & 31;
    if (w >= NN) return;
    const __half* xr = g_xt16 + (size_t)w * F;
    const float*  er = eattr + (size_t)w * F;
    float s1 = 0.f, s2 = 0.f;
    for (int i = lane * 2; i < F; i += 64) {
        float2 v = __half22float2(*(const __half2*)&xr[i]);
        s1 = fmaf(v.x, att[i],     s1);
        s1 = fmaf(v.y, att[i + 1], s1);
    }
    for (int i = lane; i < F; i += 32) s2 = fmaf(er[i], g_wv[i], s2);
#pragma unroll
    for (int off = 16; off; off >>= 1) {
        s1 += __shfl_xor_sync(0xffffffffu, s1, off);
        s2 += __shfl_xor_sync(0xffffffffu, s2, off);
    }
    if (lane == 0) { g_ax[w] = s1; g_ae[w] = s2; }
}

// ---------------- fused per-hyperedge softmax (warp per segment) ----------------
__global__ void k_seg_softmax(const int* __restrict__ ei) {
    int w    = (blockIdx.x * blockDim.x + threadIdx.x) >> 5;
    int lane = threadIdx.x & 31;
    if (w >= NN) return;
    int s = g_off_c[w], n = g_off_c[w + 1] - s;
    if (n == 0) return;
    float aec = g_ae[w];
    float m = -3.4e38f;
    for (int i = lane; i < n; i += 32) {
        int e = g_perm_c[s + i];
        float a = g_ax[ei[e]] + aec;
        a = a >= 0.f ? a : 0.2f * a;
        g_alpha[e] = a;
        m = fmaxf(m, a);
    }
#pragma unroll
    for (int o = 16; o; o >>= 1) m = fmaxf(m, __shfl_xor_sync(0xffffffffu, m, o));
    float sum = 0.f;
    for (int i = lane; i < n; i += 32) {
        int e = g_perm_c[s + i];
        float ex = expf(g_alpha[e] - m);
        g_alpha[e] = ex;
        sum += ex;
    }
#pragma unroll
    for (int o = 16; o; o >>= 1) sum += __shfl_xor_sync(0xffffffffu, sum, o);
    float inv = 1.f / (sum + 1e-16f);
    for (int i = lane; i < n; i += 32) g_alpha[g_perm_c[s + i]] *= inv;
}

// ---------------- atomic-free scatters: block per segment, fp16 gather sources ----------------
#define SCH 64
__global__ void k_scatter_e(const int* __restrict__ ei) {   // node -> hyperedge
    __shared__ float scoef[SCH];
    __shared__ int   sidx[SCH];
    int c = blockIdx.x;
    int s = g_off_c[c], end = g_off_c[c + 1];
    int n = end - s;
    float bn = n > 0 ? 1.f / (float)n : 0.f;
    int f = threadIdx.x * 4;
    float4 acc = make_float4(0.f, 0.f, 0.f, 0.f);
    while (s < end) {
        int chunk = min(SCH, end - s);
        __syncthreads();
        if ((int)threadIdx.x < chunk) {
            int e = g_perm_c[s + threadIdx.x];
            scoef[threadIdx.x] = bn * g_alpha[e];
            sidx[threadIdx.x]  = ei[e];                 // row
        }
        __syncthreads();
        for (int j = 0; j < chunk; j++) {
            float cf = scoef[j];
            uint2 u = *(const uint2*)&g_xt16[(size_t)sidx[j] * F + f];
            float2 v0 = __half22float2(*(__half2*)&u.x);
            float2 v1 = __half22float2(*(__half2*)&u.y);
            acc.x = fmaf(cf, v0.x, acc.x);
            acc.y = fmaf(cf, v0.y, acc.y);
            acc.z = fmaf(cf, v1.x, acc.z);
            acc.w = fmaf(cf, v1.y, acc.w);
        }
        s += chunk;
    }
    uint2 o;
    *(__half2*)&o.x = __floats2half2_rn(acc.x, acc.y);
    *(__half2*)&o.y = __floats2half2_rn(acc.z, acc.w);
    *(uint2*)&g_ef16[(size_t)c * F + f] = o;
}

__global__ void k_scatter_n(const int* __restrict__ ei, const float* __restrict__ bias) {
    __shared__ float scoef[SCH];
    __shared__ int   sidx[SCH];
    int r = blockIdx.x;
    int s = g_off_r[r], end = g_off_r[r + 1];
    int n = end - s;
    float dn = n > 0 ? 1.f / (float)n : 0.f;
    int f = threadIdx.x * 4;
    float4 acc = make_float4(0.f, 0.f, 0.f, 0.f);
    while (s < end) {
        int chunk = min(SCH, end - s);
        __syncthreads();
        if ((int)threadIdx.x < chunk) {
            int e = g_perm_r[s + threadIdx.x];
            scoef[threadIdx.x] = dn * g_alpha[e];
            sidx[threadIdx.x]  = ei[NNZ + e];           // col
        }
        __syncthreads();
        for (int j = 0; j < chunk; j++) {
            float cf = scoef[j];
            uint2 u = *(const uint2*)&g_ef16[(size_t)sidx[j] * F + f];
            float2 v0 = __half22float2(*(__half2*)&u.x);
            float2 v1 = __half22float2(*(__half2*)&u.y);
            acc.x = fmaf(cf, v0.x, acc.x);
            acc.y = fmaf(cf, v0.y, acc.y);
            acc.z = fmaf(cf, v1.x, acc.z);
            acc.w = fmaf(cf, v1.y, acc.w);
        }
        s += chunk;
    }
    // fused: + bias, leaky relu 0.01; write fp32 (GN input) and fp16 (GEMM input)
    float4 b4 = *(const float4*)&bias[f];
    acc.x += b4.x; acc.y += b4.y; acc.z += b4.z; acc.w += b4.w;
    acc.x = acc.x >= 0.f ? acc.x : 0.01f * acc.x;
    acc.y = acc.y >= 0.f ? acc.y : 0.01f * acc.y;
    acc.z = acc.z >= 0.f ? acc.z : 0.01f * acc.z;
    acc.w = acc.w >= 0.f ? acc.w : 0.01f * acc.w;
    *(float4*)&g_h[(size_t)r * F + f] = acc;
    __half2* hp = (__half2*)&g_h16[(size_t)r * F + f];
    hp[0] = __floats2half2_rn(acc.x, acc.y);
    hp[1] = __floats2half2_rn(acc.z, acc.w);
}

// ---------------- transpose src[NN,C] -> fp16 dst[c*NN + r] ----------------
__global__ void k_transpose(const float* __restrict__ src, int C, __half* __restrict__ dst) {
    __shared__ float t[32][33];
    int c0 = blockIdx.x * 32, r0 = blockIdx.y * 32;
    int tx = threadIdx.x, ty = threadIdx.y;
#pragma unroll
    for (int i = 0; i < 4; i++)
        t[ty + 8 * i][tx] = src[(size_t)(r0 + ty + 8 * i) * C + c0 + tx];
    __syncthreads();
#pragma unroll
    for (int i = 0; i < 4; i++)
        dst[(size_t)(c0 + ty + 8 * i) * NN + r0 + tx] = __float2half_rn(t[tx][ty + 8 * i]);
}

// ---------------- score finalize + folded classifier ----------------
__global__ void k_score_final(const float* __restrict__ b2, const float* __restrict__ center) {
    int d = blockIdx.x * blockDim.x + threadIdx.x;
    if (d >= DCAT) return;
    float r = g_score[d] + b2[0];
    float sg = 1.f / (1.f + expf(-r));
    g_score[d] = sg - center[d];
}

__global__ void k_wp(const float* __restrict__ clsW) {
    int idx = blockIdx.x * blockDim.x + threadIdx.x;
    if (idx >= OUTD * DCAT) return;
    g_wp[idx] = clsW[idx] * g_score[idx % DCAT];
}

__global__ void k_logits(const float* __restrict__ x, const float* __restrict__ clsb,
                         float* __restrict__ out) {
    int n    = (blockIdx.x * blockDim.x + threadIdx.x) >> 5;
    int lane = threadIdx.x & 31;
    if (n >= NN) return;
    float acc[OUTD];
#pragma unroll
    for (int o = 0; o < OUTD; o++) acc[o] = 0.f;

    const float* xr = x + (size_t)n * F;
#pragma unroll
    for (int it = 0; it < 6; it++) {
        int i = lane * 4 + it * 128;
        float4 v = *(const float4*)&xr[i];
#pragma unroll
        for (int o = 0; o < OUTD; o++) {
            float4 w = *(const float4*)&g_wp[o * DCAT + i];
            acc[o] += v.x * w.x + v.y * w.y + v.z * w.z + v.w * w.w;
        }
    }
    const float* o1 = g_out1 + (size_t)n * HIDD;
#pragma unroll
    for (int it = 0; it < 3; it++) {
        int i = lane * 4 + it * 128;
        float4 v = *(const float4*)&o1[i];
#pragma unroll
        for (int o = 0; o < OUTD; o++) {
            float4 w = *(const float4*)&g_wp[o * DCAT + F + i];
            acc[o] += v.x * w.x + v.y * w.y + v.z * w.z + v.w * w.w;
        }
    }
    const float* o2 = g_out2 + (size_t)n * HIDD;
#pragma unroll
    for (int it = 0; it < 3; it++) {
        int i = lane * 4 + it * 128;
        float4 v = *(const float4*)&o2[i];
#pragma unroll
        for (int o = 0; o < OUTD; o++) {
            float4 w = *(const float4*)&g_wp[o * DCAT + F + HIDD + i];
            acc[o] += v.x * w.x + v.y * w.y + v.z * w.z + v.w * w.w;
        }
    }
#pragma unroll
    for (int o = 0; o < OUTD; o++) {
        float v = acc[o];
#pragma unroll
        for (int off = 16; off; off >>= 1) v += __shfl_xor_sync(0xffffffffu, v, off);
        if (lane == 0) out[(size_t)n * OUTD + o] = v + clsb[o];
    }
}

// ---------------- host-side driver ----------------
static const int SMEM_G = STAGES * (ABYTES + 128 * 128) + 1024;   // 99328 -> 2 CTAs/SM

static void run_conv(const float* feat_in, const int* ei, const float* eattr,
                     const float* gw, const float* gb, const float* gms,
                     const float* W, const float* att, const float* hb,
                     __half* p_xn16, __half* p_wh, __half* p_xt16)
{
    k_zero_gn<<<1, 768>>>();
    k_gn_reduce<<<NN / 64, 768>>>(feat_in);
    k_gn_apply<<<NN * F / 256, 256>>>(feat_in, gw, gb, gms);
    k_cvt_h<<<(F * F / 4 + 255) / 256, 256>>>((const float4*)W, (__half2*)p_wh, F * F / 4);
    k_watt<<<(F + 255) / 256, 256>>>(W, att);
    k_gemm<<<dim3(F / 128, NN / 128), 256, SMEM_G>>>(
        p_xn16, p_wh, p_xt16, F, F, 0, 0, nullptr, nullptr, nullptr);
    k_gemv_att<<<NN / 8, 256>>>(att, eattr);
    k_seg_softmax<<<NN / 8, 256>>>(ei);
    k_scatter_e<<<NN, 192>>>(ei);
    k_scatter_n<<<NN, 192>>>(ei, hb);
}

extern "C" void kernel_launch(void* const* d_in, const int* in_sizes, int n_in,
                              void* d_out, int out_size) {
    const float* x       = (const float*)d_in[0];
    const int*   ei      = (const int*)  d_in[1];
    const float* eattr   = (const float*)d_in[2];
    const float* gn1_w   = (const float*)d_in[3];
    const float* gn1_b   = (const float*)d_in[4];
    const float* gn1_ms  = (const float*)d_in[5];
    const float* gn2_w   = (const float*)d_in[6];
    const float* gn2_b   = (const float*)d_in[7];
    const float* gn2_ms  = (const float*)d_in[8];
    const float* hg1_W   = (const float*)d_in[9];
    const float* hg1_att = (const float*)d_in[10];
    const float* hg1_b   = (const float*)d_in[11];
    const float* hg2_W   = (const float*)d_in[12];
    const float* hg2_att = (const float*)d_in[13];
    const float* hg2_b   = (const float*)d_in[14];
    const float* fc1_W   = (const float*)d_in[15];
    const float* fc1_b   = (const float*)d_in[16];
    const float* fc2_W   = (const float*)d_in[17];
    const float* fc2_b   = (const float*)d_in[18];
    const float* attn_W1 = (const float*)d_in[19];
    const float* attn_b1 = (const float*)d_in[20];
    const float* attn_W2 = (const float*)d_in[21];
    const float* attn_b2 = (const float*)d_in[22];
    const float* cls_W   = (const float*)d_in[23];
    const float* cls_b   = (const float*)d_in[24];
    const float* center  = (const float*)d_in[25];
    float*       out     = (float*)d_out;

    cudaFuncSetAttribute(k_gemm, cudaFuncAttributeMaxDynamicSharedMemorySize, SMEM_G);

    float *p_h, *p_out1, *p_out2, *p_score;
    __half *p_xn16, *p_xt16, *p_h16, *p_catT16, *p_w1h, *p_wh, *p_fwh;
    cudaGetSymbolAddress((void**)&p_h,       g_h);
    cudaGetSymbolAddress((void**)&p_out1,    g_out1);
    cudaGetSymbolAddress((void**)&p_out2,    g_out2);
    cudaGetSymbolAddress((void**)&p_score,   g_score);
    cudaGetSymbolAddress((void**)&p_xn16,    g_xn16);
    cudaGetSymbolAddress((void**)&p_xt16,    g_xt16);
    cudaGetSymbolAddress((void**)&p_h16,     g_h16);
    cudaGetSymbolAddress((void**)&p_catT16,  g_catT16);
    cudaGetSymbolAddress((void**)&p_w1h,     g_w1h);
    cudaGetSymbolAddress((void**)&p_wh,      g_wh);
    cudaGetSymbolAddress((void**)&p_fwh,     g_fwh);

    // ---- CSR build (once) + big one-time fp16 conversion ----
    k_csr_zero<<<NN / 256, 256>>>();
    k_csr_count<<<NNZ / 256, 256>>>(ei);
    k_scan2<<<2, 1024>>>();
    k_csr_place<<<NNZ / 256, 256>>>(ei);
    k_cvt_h<<<(int)((size_t)NN * NN / 4 / 256), 256>>>((const float4*)attn_W1, (__half2*)p_w1h,
                                                       (int)((size_t)NN * NN / 4));

    // ---- conv1 + fc1 ----
    run_conv(x, ei, eattr, gn1_w, gn1_b, gn1_ms, hg1_W, hg1_att, hg1_b, p_xn16, p_wh, p_xt16);
    k_cvt_h<<<(HIDD * F / 4 + 255) / 256, 256>>>((const float4*)fc1_W, (__half2*)p_fwh, HIDD * F / 4);
    k_gemm<<<dim3(HIDD / 128, NN / 128), 256, SMEM_G>>>(
        p_h16, p_fwh, p_out1, HIDD, F, 1, 0, fc1_b, nullptr, nullptr);

    // ---- conv2 (graphnorm reads fp32 g_h = h1 before scatter_n overwrites it) + fc2 ----
    run_conv(p_h, ei, eattr, gn2_w, gn2_b, gn2_ms, hg2_W, hg2_att, hg2_b, p_xn16, p_wh, p_xt16);
    k_cvt_h<<<(HIDD * F / 4 + 255) / 256, 256>>>((const float4*)fc2_W, (__half2*)p_fwh, HIDD * F / 4);
    k_gemm<<<dim3(HIDD / 128, NN / 128), 256, SMEM_G>>>(
        p_h16, p_fwh, p_out2, HIDD, F, 1, 0, fc2_b, nullptr, nullptr);

    // ---- catT = [x; out1; out2]^T in fp16 (node-contiguous) ----
    k_transpose<<<dim3(F / 32,    NN / 32), dim3(32, 8)>>>(x,      F,    p_catT16);
    k_transpose<<<dim3(HIDD / 32, NN / 32), dim3(32, 8)>>>(p_out1, HIDD, p_catT16 + (size_t)F * NN);
    k_transpose<<<dim3(HIDD / 32, NN / 32), dim3(32, 8)>>>(p_out2, HIDD, p_catT16 + (size_t)(F + HIDD) * NN);

    // ---- attention: score[d] = sum_j relu(catT@W1^T + b1)[d,j] * W2[j] ----
    // swapped grid: row tiles fastest -> consecutive CTAs share the same W1 panel (L2 reuse)
    k_zero_score<<<(DCAT + 255) / 256, 256>>>();
    k_gemm<<<dim3(DCAT / 128, NN / 128), 256, SMEM_G>>>(
        p_catT16, p_w1h, nullptr, NN, NN, 2, 1, attn_b1, attn_W2, p_score);
    k_score_final<<<(DCAT + 255) / 256, 256>>>(attn_b2, center);

    // ---- classifier with score folded into weights ----
    k_wp<<<(OUTD * DCAT + 255) / 256, 256>>>(cls_W);
    k_logits<<<NN * 32 / 256, 256>>>(x, cls_b, out);
}